// round 11
// baseline (speedup 1.0000x reference)
#include <cuda_runtime.h>
#include <math.h>

#define BB 64
#define TT 2048
#define ENC_DIM 512
#define ATT_DIM 128
#define RNN_DIM 1024
#define N_FILT 32
#define KSIZE 31
#define PADC 15
#define WIN 32
#define WLMAX 65
#define NTL_PAD 36          // padded per-rank timestep rows (mult of 4)
#define DTP 129             // dense_t row stride (conflict-free)
#define AWLEN 66            // staged aw length per channel

// ---- dynamic smem layout (floats), per CTA (one rank) ----
#define F_MEM  0                                   // 33*512 = 16896
#define F_PM   (F_MEM + 33 * ENC_DIM)              // 36*128 = 4608
#define F_DT   (F_PM + NTL_PAD * ATT_DIM)          // 32*129 = 4128
#define F_CWT  (F_DT + N_FILT * DTP)               // 62*32  = 1984
#define F_H    (F_CWT + KSIZE * 2 * N_FILT)        // 1024
#define F_CONV (F_H + RNN_DIM)                     // 32*36  = 1152
#define F_AW   (F_CONV + N_FILT * NTL_PAD)         // 2*96
#define F_Q    (F_AW + 2 * 96)                     // 128
#define F_V    (F_Q + ATT_DIM)                     // 128
#define F_E    (F_V + ATT_DIM)                     // 72
#define F_MK   (F_E + 72)                          // 40
#define F_W    (F_MK + 40)                         // 72
#define F_CTX  (F_W + 72)                          // 512
#define F_ST   (F_CTX + ENC_DIM)                   // 8 (stats: [rank*4 + {m,S,np}])
#define F_END  (F_ST + 8)
#define SMEM_BYTES (F_END * 4)

__device__ __forceinline__ float ftanh(float x) {
    float a = fabsf(x);
    float t = __expf(-2.0f * a);
    float r = __fdividef(1.0f - t, 1.0f + t);
    return copysignf(r, x);
}

__device__ __forceinline__ void cp16(unsigned dst, const void* src) {
    asm volatile("cp.async.cg.shared.global [%0], [%1], 16;" :: "r"(dst), "l"(src));
}
__device__ __forceinline__ unsigned smem_u32(const void* p) {
    return (unsigned)__cvta_generic_to_shared(p);
}
__device__ __forceinline__ unsigned mapa_peer(unsigned addr, unsigned peer) {
    unsigned r;
    asm("mapa.shared::cluster.u32 %0, %1, %2;" : "=r"(r) : "r"(addr), "r"(peer));
    return r;
}
__device__ __forceinline__ void st_cluster_f32(unsigned addr, float v) {
    asm volatile("st.shared::cluster.f32 [%0], %1;" :: "r"(addr), "f"(v));
}
__device__ __forceinline__ void cluster_sync() {
    asm volatile("barrier.cluster.arrive.aligned;" ::: "memory");
    asm volatile("barrier.cluster.wait.aligned;" ::: "memory");
}

__global__ __launch_bounds__(256, 1) __cluster_dims__(2, 1, 1)
void attn_fused_kernel(
    const float* __restrict__ h,
    const float* __restrict__ memory,
    const float* __restrict__ pm,
    const float* __restrict__ awcat,
    const unsigned char* __restrict__ maskp,
    const int* __restrict__ mlen,
    const float* __restrict__ cpos,
    const float* __restrict__ convw,
    const float* __restrict__ densew,
    const float* __restrict__ queryw,
    const float* __restrict__ vw,
    const float* __restrict__ posoff,
    float* __restrict__ out)
{
    extern __shared__ float sm[];
    __shared__ int s_fb;

    const int b    = blockIdx.x >> 1;
    const unsigned rank = blockIdx.x & 1;
    const unsigned peer = rank ^ 1;
    const int tid  = threadIdx.x;
    const int lane = tid & 31;
    const int wid  = tid >> 5;

    float* mem_sh  = sm + F_MEM;
    float* pm_sh   = sm + F_PM;
    float* dense_t = sm + F_DT;
    float* cwt_sh  = sm + F_CWT;
    float* h_sh    = sm + F_H;
    float* conv_sh = sm + F_CONV;
    float* aw0_sh  = sm + F_AW;
    float* aw1_sh  = sm + F_AW + 96;
    float* q_sh    = sm + F_Q;
    float* v_sh    = sm + F_V;
    float* e_sh    = sm + F_E;
    float* mk_sh   = sm + F_MK;
    float* w_sh    = sm + F_W;
    float* ctxbuf  = sm + F_CTX;
    float* st_sh   = sm + F_ST;

    // ---- phase 0a: EVERY thread computes the window (broadcast LDGs) ----
    int start, wl;
    {
        float cp      = cpos[b] + posoff[0];
        float max_end = (float)(mlen[b] - 1 - WIN);
        cp = fminf(fmaxf(cp, (float)WIN), max_end);
        float ms = rintf(fmaxf(cp - (float)WIN, 0.0f));
        start = (int)ms;
        if (start < 0) start = 0;
        if (start > TT - 1) start = TT - 1;
        int end = start + 2 * WIN;
        if (end > TT - 1) end = TT - 1;
        wl = end - start + 1;                 // == 65 for this shape
    }
    const int TL0 = rank ? 33 : 0;
    int ntl = rank ? (wl - 33) : (wl < 33 ? wl : 33);
    if (ntl < 0) ntl = 0;

    // ---- phase 0b: prefetch own pm/mem slices IMMEDIATELY (no barrier) ----
    {
        const unsigned pm_base  = smem_u32(pm_sh);
        const unsigned mem_base = smem_u32(mem_sh);
        const float4* pmsrc  = (const float4*)(pm + ((size_t)b * TT + start + TL0) * ATT_DIM);
        const float4* memsrc = (const float4*)(memory + ((size_t)b * TT + start + TL0) * ENC_DIM);
        const int n_pm4 = ntl * (ATT_DIM / 4);
        for (int i = tid; i < n_pm4; i += 256) cp16(pm_base + i * 16, pmsrc + i);
        asm volatile("cp.async.commit_group;");
        const int n_m4 = ntl * (ENC_DIM / 4);
        for (int i = tid; i < n_m4; i += 256) cp16(mem_base + i * 16, memsrc + i);
        asm volatile("cp.async.commit_group;");

        for (int j = tid; j < 2 * AWLEN; j += 256) {
            int c = (j >= AWLEN), jj = c ? j - AWLEN : j;
            int g = start + TL0 - PADC + jj;
            float v = (g >= 0 && g < TT) ? awcat[((size_t)b * 2 + c) * TT + g] : 0.f;
            (c ? aw1_sh : aw0_sh)[jj] = v;
        }
        if (tid < ntl) mk_sh[tid] = maskp[(size_t)b * TT + start + TL0 + tid] ? 1.f : 0.f;
    }

    // ---- phase 0c: stage static weights ----
    {
        const float4* hg = (const float4*)(h + (size_t)b * RNN_DIM);
        ((float4*)h_sh)[tid] = hg[tid];
        for (int i = tid; i < N_FILT * 2 * KSIZE; i += 256) {
            int f = i / (2 * KSIZE), rr = i % (2 * KSIZE);
            int c = rr / KSIZE, k = rr % KSIZE;
            cwt_sh[(k * 2 + c) * N_FILT + f] = convw[i];
        }
        for (int i = tid; i < ATT_DIM * N_FILT; i += 256) {
            int a = i >> 5, f = i & 31;
            dense_t[f * DTP + a] = densew[i];
        }
        if (tid < ATT_DIM) v_sh[tid] = vw[tid];
    }
    __syncthreads();                          // S0: h/aw/weights staged

    // ---- phase 1: full query GEMV (all 128 rows, 16 per warp, 4-row ILP) ----
    {
        const float4* h4 = (const float4*)h_sh;
        #pragma unroll 1
        for (int g = 0; g < 4; g++) {
            const int a0 = wid * 16 + g * 4;
            const float4* r0 = (const float4*)(queryw + (size_t)a0 * RNN_DIM);
            const float4* r1 = (const float4*)(queryw + (size_t)(a0 + 1) * RNN_DIM);
            const float4* r2 = (const float4*)(queryw + (size_t)(a0 + 2) * RNN_DIM);
            const float4* r3 = (const float4*)(queryw + (size_t)(a0 + 3) * RNN_DIM);
            float acc0 = 0.f, acc1 = 0.f, acc2 = 0.f, acc3 = 0.f;
            #pragma unroll
            for (int k = 0; k < 8; k++) {
                const int idx = lane + k * 32;
                float4 hv = h4[idx];
                float4 w0 = r0[idx], w1 = r1[idx], w2 = r2[idx], w3 = r3[idx];
                acc0 += hv.x * w0.x + hv.y * w0.y + hv.z * w0.z + hv.w * w0.w;
                acc1 += hv.x * w1.x + hv.y * w1.y + hv.z * w1.z + hv.w * w1.w;
                acc2 += hv.x * w2.x + hv.y * w2.y + hv.z * w2.z + hv.w * w2.w;
                acc3 += hv.x * w3.x + hv.y * w3.y + hv.z * w3.z + hv.w * w3.w;
            }
            #pragma unroll
            for (int o = 16; o; o >>= 1) {
                acc0 += __shfl_down_sync(0xffffffffu, acc0, o);
                acc1 += __shfl_down_sync(0xffffffffu, acc1, o);
                acc2 += __shfl_down_sync(0xffffffffu, acc2, o);
                acc3 += __shfl_down_sync(0xffffffffu, acc3, o);
            }
            if (lane == 0) {
                q_sh[a0] = acc0; q_sh[a0 + 1] = acc1;
                q_sh[a0 + 2] = acc2; q_sh[a0 + 3] = acc3;
            }
        }
    }

    // ---- phase 2: conv (4 filters/warp, tl = lane, padded rows 0..35) ----
    {
        const int f0 = wid * 4;
        for (int tl = lane; tl < NTL_PAD; tl += 32) {
            float acc[4] = {0, 0, 0, 0};
            #pragma unroll
            for (int k = 0; k < KSIZE; k++) {
                const float a0v = aw0_sh[tl + k];
                const float a1v = aw1_sh[tl + k];
                const float4 w0 = *(const float4*)(cwt_sh + (k * 2 + 0) * N_FILT + f0);
                const float4 w1 = *(const float4*)(cwt_sh + (k * 2 + 1) * N_FILT + f0);
                acc[0] += a0v * w0.x + a1v * w1.x;
                acc[1] += a0v * w0.y + a1v * w1.y;
                acc[2] += a0v * w0.z + a1v * w1.z;
                acc[3] += a0v * w0.w + a1v * w1.w;
            }
            #pragma unroll
            for (int j = 0; j < 4; j++) conv_sh[(f0 + j) * NTL_PAD + tl] = acc[j];
        }
    }
    asm volatile("cp.async.wait_group 1;");   // pm slice (this thread)
    __syncthreads();                          // S1: q + conv + pm ready

    float* out_w = out + (size_t)BB * ENC_DIM + (size_t)b * TT;

    // ---- phase 3: energies for own timesteps (4-t x 4-dim blocking) ----
    {
        const float qv0 = q_sh[lane],      qv1 = q_sh[lane + 32];
        const float qv2 = q_sh[lane + 64], qv3 = q_sh[lane + 96];
        const float vv0 = v_sh[lane],      vv1 = v_sh[lane + 32];
        const float vv2 = v_sh[lane + 64], vv3 = v_sh[lane + 96];
        for (int t0 = wid * 4; t0 < ntl; t0 += 32) {
            float s[4][4];
            #pragma unroll
            for (int i = 0; i < 4; i++) {
                const float* p = pm_sh + (t0 + i) * ATT_DIM;
                s[i][0] = qv0 + p[lane];
                s[i][1] = qv1 + p[lane + 32];
                s[i][2] = qv2 + p[lane + 64];
                s[i][3] = qv3 + p[lane + 96];
            }
            #pragma unroll 8
            for (int f = 0; f < N_FILT; f++) {
                const float4 c4 = *(const float4*)(conv_sh + f * NTL_PAD + t0);
                const float* dt = dense_t + f * DTP;
                const float d0 = dt[lane],      d1 = dt[lane + 32];
                const float d2 = dt[lane + 64], d3 = dt[lane + 96];
                s[0][0] += d0 * c4.x; s[0][1] += d1 * c4.x; s[0][2] += d2 * c4.x; s[0][3] += d3 * c4.x;
                s[1][0] += d0 * c4.y; s[1][1] += d1 * c4.y; s[1][2] += d2 * c4.y; s[1][3] += d3 * c4.y;
                s[2][0] += d0 * c4.z; s[2][1] += d1 * c4.z; s[2][2] += d2 * c4.z; s[2][3] += d3 * c4.z;
                s[3][0] += d0 * c4.w; s[3][1] += d1 * c4.w; s[3][2] += d2 * c4.w; s[3][3] += d3 * c4.w;
            }
            float a[4];
            #pragma unroll
            for (int i = 0; i < 4; i++)
                a[i] = vv0 * ftanh(s[i][0]) + vv1 * ftanh(s[i][1])
                     + vv2 * ftanh(s[i][2]) + vv3 * ftanh(s[i][3]);
            #pragma unroll
            for (int o = 16; o; o >>= 1) {
                a[0] += __shfl_xor_sync(0xffffffffu, a[0], o);
                a[1] += __shfl_xor_sync(0xffffffffu, a[1], o);
                a[2] += __shfl_xor_sync(0xffffffffu, a[2], o);
                a[3] += __shfl_xor_sync(0xffffffffu, a[3], o);
            }
            if (lane < 4 && t0 + lane < ntl) {
                float av = (lane == 0) ? a[0] : (lane == 1) ? a[1] : (lane == 2) ? a[2] : a[3];
                if (mk_sh[t0 + lane] != 0.f) av = -1e9f;
                e_sh[TL0 + t0 + lane] = av;
            }
        }
        // zero-fill own out_w half, SKIPPING window cells (owned by tl-writer)
        const int wend = start + wl - 1;
        const int t4 = (int)rank * 1024 + tid * 4;
        if (t4 + 3 < start || t4 > wend) {
            ((float4*)out_w)[rank * 256 + tid] = make_float4(0.f, 0.f, 0.f, 0.f);
        } else {
            #pragma unroll
            for (int j = 0; j < 4; j++) {
                const int t = t4 + j;
                if (t < start || t > wend) out_w[t] = 0.f;
            }
        }
    }
    __syncthreads();                          // S2: e_sh ready

    // ---- phase 4: partial softmax stats (warp 0), exchange 3 floats ----
    if (wid == 0) {
        float e0 = (lane < ntl)      ? e_sh[TL0 + lane]      : -3.4e38f;
        float e1 = (lane + 32 < ntl) ? e_sh[TL0 + lane + 32] : -3.4e38f;
        float m = fmaxf(e0, e1);
        #pragma unroll
        for (int o = 16; o; o >>= 1) m = fmaxf(m, __shfl_xor_sync(0xffffffffu, m, o));
        float x0 = (lane < ntl)      ? __expf(e0 - m) : 0.f;
        float x1 = (lane + 32 < ntl) ? __expf(e1 - m) : 0.f;
        float S  = x0 + x1;
        float np = x0 * (float)(start + TL0 + lane)
                 + x1 * (float)(start + TL0 + lane + 32);
        #pragma unroll
        for (int o = 16; o; o >>= 1) {
            S  += __shfl_xor_sync(0xffffffffu, S, o);
            np += __shfl_xor_sync(0xffffffffu, np, o);
        }
        if (lane < ntl)      w_sh[TL0 + lane]      = x0;
        if (lane + 32 < ntl) w_sh[TL0 + lane + 32] = x1;
        if (lane == 0) {
            const int so = (int)rank * 4;
            st_sh[so] = m; st_sh[so + 1] = S; st_sh[so + 2] = np;
            const unsigned ps = mapa_peer(smem_u32(st_sh), peer) + so * 4;
            st_cluster_f32(ps,     m);
            st_cluster_f32(ps + 4, S);
            st_cluster_f32(ps + 8, np);
        }
    }
    cluster_sync();                           // C1: stats in both CTAs

    // ---- phase 5: combine stats, rescale own weights (warp 0) ----
    if (wid == 0) {
        const float m0 = st_sh[0], S0 = st_sh[1], np0 = st_sh[2];
        const float m1 = st_sh[4], S1 = st_sh[5], np1 = st_sh[6];
        const float m = fmaxf(m0, m1);
        if (m <= -1e9f) {
            if (lane == 0) s_fb = 1;
        } else {
            if (lane == 0) s_fb = 0;
            const float c0 = __expf(m0 - m), c1 = __expf(m1 - m);
            const float inv = __fdividef(1.0f, S0 * c0 + S1 * c1);
            const float scale = (rank ? c1 : c0) * inv;
            if (lane < ntl)      w_sh[TL0 + lane]      *= scale;
            if (lane + 32 < ntl) w_sh[TL0 + lane + 32] *= scale;
            if (lane == 0 && rank == 0)
                out[(size_t)BB * ENC_DIM + (size_t)BB * TT + b] = (np0 * c0 + np1 * c1) * inv;
        }
    }
    asm volatile("cp.async.wait_group 0;");   // mem slice complete
    __syncthreads();                          // S3: w_sh + s_fb ready

    float* out_ctx = out + (size_t)b * ENC_DIM;
    const int fb = s_fb;

    // ---- phase 6: window weights (tl ownership) + context partial ----
    float4 acc = make_float4(0.f, 0.f, 0.f, 0.f);
    if (!fb) {
        if (tid < ntl) out_w[start + TL0 + tid] = w_sh[TL0 + tid];
        if (tid < 128) {
            const float4* m4 = (const float4*)mem_sh;
            #pragma unroll 4
            for (int i = 0; i < ntl; i++) {
                const float wv = w_sh[TL0 + i];
                const float4 v = m4[i * (ENC_DIM / 4) + tid];
                acc.x += wv * v.x; acc.y += wv * v.y;
                acc.z += wv * v.z; acc.w += wv * v.w;
            }
        }
    } else {
        const float u = 1.0f / (float)TT;
        ((float4*)out_w)[rank * 256 + tid] = make_float4(u, u, u, u);
        if (rank == 0 && tid == 0)
            out[(size_t)BB * ENC_DIM + (size_t)BB * TT + b] = (float)(TT - 1) * 0.5f;
        if (tid < 128) {
            const float4* mg = (const float4*)(memory
                + ((size_t)b * TT + (size_t)rank * 1024) * ENC_DIM);
            for (int t = 0; t < 1024; t++) {
                const float4 v = mg[(size_t)t * (ENC_DIM / 4) + tid];
                acc.x += v.x; acc.y += v.y; acc.z += v.z; acc.w += v.w;
            }
            acc.x *= u; acc.y *= u; acc.z *= u; acc.w *= u;
        }
    }
    if (rank == 1 && tid < 128) {
        const unsigned cb = mapa_peer(smem_u32(ctxbuf), peer) + tid * 16;
        st_cluster_f32(cb,      acc.x);
        st_cluster_f32(cb + 4,  acc.y);
        st_cluster_f32(cb + 8,  acc.z);
        st_cluster_f32(cb + 12, acc.w);
    }
    cluster_sync();                           // C2: rank1 partial visible
    if (rank == 0 && tid < 128) {
        const float4 p = ((const float4*)ctxbuf)[tid];
        acc.x += p.x; acc.y += p.y; acc.z += p.z; acc.w += p.w;
        ((float4*)out_ctx)[tid] = acc;
    }
}

extern "C" void kernel_launch(void* const* d_in, const int* in_sizes, int n_in,
                              void* d_out, int out_size) {
    const float*         h      = (const float*)d_in[0];
    const float*         memory = (const float*)d_in[1];
    const float*         pm     = (const float*)d_in[2];
    const float*         awcat  = (const float*)d_in[3];
    const unsigned char* maskp  = (const unsigned char*)d_in[4];
    const int*           mlen   = (const int*)d_in[5];
    const float*         cpos   = (const float*)d_in[6];
    const float*         convw  = (const float*)d_in[7];
    const float*         densew = (const float*)d_in[8];
    const float*         queryw = (const float*)d_in[9];
    const float*         vw     = (const float*)d_in[10];
    const float*         posoff = (const float*)d_in[11];
    float* out = (float*)d_out;

    cudaFuncSetAttribute(attn_fused_kernel,
                         cudaFuncAttributeMaxDynamicSharedMemorySize, SMEM_BYTES);
    attn_fused_kernel<<<2 * BB, 256, SMEM_BYTES>>>(h, memory, pm, awcat, maskp,
                                                   mlen, cpos, convw, densew,
                                                   queryw, vw, posoff, out);
}

// round 12
// speedup vs baseline: 1.1009x; 1.1009x over previous
#include <cuda_runtime.h>
#include <math.h>

#define BB 64
#define TT 2048
#define ENC_DIM 512
#define ATT_DIM 128
#define RNN_DIM 1024
#define N_FILT 32
#define KSIZE 31
#define PADC 15
#define WIN 32
#define WLMAX 65
#define TPAD 68             // padded timestep rows (mult of 4)
#define HDIM 64             // dims per rank
#define DTP 68              // dense_t row stride
#define AWLEN 98            // staged aw length per channel (67+31)

// ---- dynamic smem layout (floats), per CTA ----
#define F_MEM  0                                   // 33*512 = 16896
#define F_PM   (F_MEM + 33 * ENC_DIM)              // 68*64  = 4352
#define F_DT   (F_PM + TPAD * HDIM)                // 32*68  = 2176
#define F_CWT  (F_DT + N_FILT * DTP)               // 62*32  = 1984
#define F_H    (F_CWT + KSIZE * 2 * N_FILT)        // 1024
#define F_CONV (F_H + RNN_DIM)                     // 32*68  = 2176
#define F_AW   (F_CONV + N_FILT * TPAD)            // 2*100
#define F_Q    (F_AW + 2 * 100)                    // 64
#define F_V    (F_Q + HDIM)                        // 64
#define F_PE   (F_V + HDIM)                        // 2*68 partial e
#define F_MK   (F_PE + 2 * TPAD)                   // 68
#define F_W    (F_MK + TPAD)                       // 68
#define F_CTX  (F_W + TPAD)                        // 512
#define F_END  (F_CTX + ENC_DIM)
#define SMEM_BYTES (F_END * 4)                     // ~119 KB

__device__ __forceinline__ float ftanh(float x) {
    float a = fabsf(x);
    float t = __expf(-2.0f * a);
    float r = __fdividef(1.0f - t, 1.0f + t);
    return copysignf(r, x);
}

__device__ __forceinline__ void cp16(unsigned dst, const void* src) {
    asm volatile("cp.async.cg.shared.global [%0], [%1], 16;" :: "r"(dst), "l"(src));
}
__device__ __forceinline__ unsigned smem_u32(const void* p) {
    return (unsigned)__cvta_generic_to_shared(p);
}
__device__ __forceinline__ unsigned mapa_peer(unsigned addr, unsigned peer) {
    unsigned r;
    asm("mapa.shared::cluster.u32 %0, %1, %2;" : "=r"(r) : "r"(addr), "r"(peer));
    return r;
}
__device__ __forceinline__ void st_cluster_f32(unsigned addr, float v) {
    asm volatile("st.shared::cluster.f32 [%0], %1;" :: "r"(addr), "f"(v));
}
__device__ __forceinline__ void cluster_sync() {
    asm volatile("barrier.cluster.arrive.aligned;" ::: "memory");
    asm volatile("barrier.cluster.wait.aligned;" ::: "memory");
}

__global__ __launch_bounds__(256, 1) __cluster_dims__(2, 1, 1)
void attn_fused_kernel(
    const float* __restrict__ h,
    const float* __restrict__ memory,
    const float* __restrict__ pm,
    const float* __restrict__ awcat,
    const unsigned char* __restrict__ maskp,
    const int* __restrict__ mlen,
    const float* __restrict__ cpos,
    const float* __restrict__ convw,
    const float* __restrict__ densew,
    const float* __restrict__ queryw,
    const float* __restrict__ vw,
    const float* __restrict__ posoff,
    float* __restrict__ out)
{
    extern __shared__ float sm[];
    __shared__ int s_fb;

    const int b    = blockIdx.x >> 1;
    const unsigned rank = blockIdx.x & 1;
    const unsigned peer = rank ^ 1;
    const int tid  = threadIdx.x;
    const int lane = tid & 31;
    const int wid  = tid >> 5;

    float* mem_sh  = sm + F_MEM;
    float* pm_sh   = sm + F_PM;
    float* dense_t = sm + F_DT;
    float* cwt_sh  = sm + F_CWT;
    float* h_sh    = sm + F_H;
    float* conv_sh = sm + F_CONV;
    float* aw0_sh  = sm + F_AW;
    float* aw1_sh  = sm + F_AW + 100;
    float* q_sh    = sm + F_Q;
    float* v_sh    = sm + F_V;
    float* pe_sh   = sm + F_PE;     // [2][TPAD] partial energies by rank
    float* mk_sh   = sm + F_MK;
    float* w_sh    = sm + F_W;
    float* ctxbuf  = sm + F_CTX;

    // ---- phase 0a: every thread computes the window (broadcast LDGs) ----
    int start, wl;
    {
        float cp      = cpos[b] + posoff[0];
        float max_end = (float)(mlen[b] - 1 - WIN);
        cp = fminf(fmaxf(cp, (float)WIN), max_end);
        float ms = rintf(fmaxf(cp - (float)WIN, 0.0f));
        start = (int)ms;
        if (start < 0) start = 0;
        if (start > TT - 1) start = TT - 1;
        int end = start + 2 * WIN;
        if (end > TT - 1) end = TT - 1;
        wl = end - start + 1;                 // == 65 for this shape
    }
    const int TL0 = rank ? 33 : 0;            // own timestep half (context/out_w)
    int ntl = rank ? (wl - 33) : (wl < 33 ? wl : 33);
    if (ntl < 0) ntl = 0;

    // ---- phase 0b: prefetch immediately (no preceding barrier) ----
    {
        const unsigned pm_base  = smem_u32(pm_sh);
        const unsigned mem_base = smem_u32(mem_sh);
        // pm: strided slice — all wl timesteps, own 64 dims
        const float* pmsrc = pm + ((size_t)b * TT + start) * ATT_DIM + rank * HDIM;
        const int n_pmc = wl * (HDIM / 4);    // 16 chunks per row
        for (int i = tid; i < n_pmc; i += 256) {
            const int row = i >> 4, col = i & 15;
            cp16(pm_base + (unsigned)(row * (HDIM * 4) + col * 16),
                 pmsrc + (size_t)row * ATT_DIM + col * 4);
        }
        asm volatile("cp.async.commit_group;");
        // memory: own timestep half, full ENC_DIM
        const float4* memsrc = (const float4*)(memory + ((size_t)b * TT + start + TL0) * ENC_DIM);
        const int n_m4 = ntl * (ENC_DIM / 4);
        for (int i = tid; i < n_m4; i += 256) cp16(mem_base + i * 16, memsrc + i);
        asm volatile("cp.async.commit_group;");

        // aw for ALL timesteps 0..67 (+30 halo)
        for (int j = tid; j < 2 * AWLEN; j += 256) {
            int c = (j >= AWLEN), jj = c ? j - AWLEN : j;
            int g = start - PADC + jj;
            float v = (g >= 0 && g < TT) ? awcat[((size_t)b * 2 + c) * TT + g] : 0.f;
            (c ? aw1_sh : aw0_sh)[jj] = v;
        }
        if (tid < wl) mk_sh[tid] = maskp[(size_t)b * TT + start + tid] ? 1.f : 0.f;
    }

    // ---- phase 0c: stage static weights (own-dim slices) ----
    {
        const float4* hg = (const float4*)(h + (size_t)b * RNN_DIM);
        ((float4*)h_sh)[tid] = hg[tid];
        for (int i = tid; i < N_FILT * 2 * KSIZE; i += 256) {
            int f = i / (2 * KSIZE), rr = i % (2 * KSIZE);
            int c = rr / KSIZE, k = rr % KSIZE;
            cwt_sh[(k * 2 + c) * N_FILT + f] = convw[i];
        }
        // densew[a][f] for a in own 64 dims -> dense_t[f][alocal]
        for (int i = tid; i < HDIM * N_FILT; i += 256) {
            int al = i >> 5, f = i & 31;
            dense_t[f * DTP + al] = densew[((size_t)rank * HDIM + al) * N_FILT + f];
        }
        if (tid < HDIM) v_sh[tid] = vw[rank * HDIM + tid];
    }
    __syncthreads();                          // S0

    // ---- phase 1: query GEMV — OWN 64 rows only (8 per warp, 4-row ILP) ----
    {
        const float4* h4 = (const float4*)h_sh;
        #pragma unroll 1
        for (int g = 0; g < 2; g++) {
            const int al0 = wid * 8 + g * 4;                 // local q index
            const int a0  = rank * HDIM + al0;               // global row
            const float4* r0 = (const float4*)(queryw + (size_t)a0 * RNN_DIM);
            const float4* r1 = (const float4*)(queryw + (size_t)(a0 + 1) * RNN_DIM);
            const float4* r2 = (const float4*)(queryw + (size_t)(a0 + 2) * RNN_DIM);
            const float4* r3 = (const float4*)(queryw + (size_t)(a0 + 3) * RNN_DIM);
            float acc0 = 0.f, acc1 = 0.f, acc2 = 0.f, acc3 = 0.f;
            #pragma unroll
            for (int k = 0; k < 8; k++) {
                const int idx = lane + k * 32;
                float4 hv = h4[idx];
                float4 w0 = r0[idx], w1 = r1[idx], w2 = r2[idx], w3 = r3[idx];
                acc0 += hv.x * w0.x + hv.y * w0.y + hv.z * w0.z + hv.w * w0.w;
                acc1 += hv.x * w1.x + hv.y * w1.y + hv.z * w1.z + hv.w * w1.w;
                acc2 += hv.x * w2.x + hv.y * w2.y + hv.z * w2.z + hv.w * w2.w;
                acc3 += hv.x * w3.x + hv.y * w3.y + hv.z * w3.z + hv.w * w3.w;
            }
            #pragma unroll
            for (int o = 16; o; o >>= 1) {
                acc0 += __shfl_down_sync(0xffffffffu, acc0, o);
                acc1 += __shfl_down_sync(0xffffffffu, acc1, o);
                acc2 += __shfl_down_sync(0xffffffffu, acc2, o);
                acc3 += __shfl_down_sync(0xffffffffu, acc3, o);
            }
            if (lane == 0) {
                q_sh[al0] = acc0; q_sh[al0 + 1] = acc1;
                q_sh[al0 + 2] = acc2; q_sh[al0 + 3] = acc3;
            }
        }
    }

    // ---- phase 2: conv — ALL timesteps (4 filters/warp, tl padded 0..67) ----
    {
        const int f0 = wid * 4;
        for (int tl = lane; tl < TPAD; tl += 32) {
            float acc[4] = {0, 0, 0, 0};
            #pragma unroll
            for (int k = 0; k < KSIZE; k++) {
                const float a0v = aw0_sh[tl + k];
                const float a1v = aw1_sh[tl + k];
                const float4 w0 = *(const float4*)(cwt_sh + (k * 2 + 0) * N_FILT + f0);
                const float4 w1 = *(const float4*)(cwt_sh + (k * 2 + 1) * N_FILT + f0);
                acc[0] += a0v * w0.x + a1v * w1.x;
                acc[1] += a0v * w0.y + a1v * w1.y;
                acc[2] += a0v * w0.z + a1v * w1.z;
                acc[3] += a0v * w0.w + a1v * w1.w;
            }
            #pragma unroll
            for (int j = 0; j < 4; j++) conv_sh[(f0 + j) * TPAD + tl] = acc[j];
        }
    }
    asm volatile("cp.async.wait_group 1;");   // pm slice (this thread)
    __syncthreads();                          // S1: q + conv + pm ready

    // ---- phase 3: PARTIAL energies over own 64 dims, ALL timesteps ----
    {
        const unsigned pe_peer = mapa_peer(smem_u32(pe_sh), peer);
        const float qv0 = q_sh[lane], qv1 = q_sh[lane + 32];
        const float vv0 = v_sh[lane], vv1 = v_sh[lane + 32];
        for (int t0 = wid * 4; t0 < wl; t0 += 32) {
            float s[4][2];
            #pragma unroll
            for (int i = 0; i < 4; i++) {
                const float* p = pm_sh + (t0 + i) * HDIM;   // padded rows safe
                s[i][0] = qv0 + p[lane];
                s[i][1] = qv1 + p[lane + 32];
            }
            #pragma unroll 8
            for (int f = 0; f < N_FILT; f++) {
                const float4 c4 = *(const float4*)(conv_sh + f * TPAD + t0);
                const float* dt = dense_t + f * DTP;
                const float d0 = dt[lane], d1 = dt[lane + 32];
                s[0][0] += d0 * c4.x; s[0][1] += d1 * c4.x;
                s[1][0] += d0 * c4.y; s[1][1] += d1 * c4.y;
                s[2][0] += d0 * c4.z; s[2][1] += d1 * c4.z;
                s[3][0] += d0 * c4.w; s[3][1] += d1 * c4.w;
            }
            float a[4];
            #pragma unroll
            for (int i = 0; i < 4; i++)
                a[i] = vv0 * ftanh(s[i][0]) + vv1 * ftanh(s[i][1]);
            #pragma unroll
            for (int o = 16; o; o >>= 1) {
                a[0] += __shfl_xor_sync(0xffffffffu, a[0], o);
                a[1] += __shfl_xor_sync(0xffffffffu, a[1], o);
                a[2] += __shfl_xor_sync(0xffffffffu, a[2], o);
                a[3] += __shfl_xor_sync(0xffffffffu, a[3], o);
            }
            if (lane < 4 && t0 + lane < wl) {
                const float av = (lane == 0) ? a[0] : (lane == 1) ? a[1]
                               : (lane == 2) ? a[2] : a[3];
                const unsigned off = rank * TPAD + (unsigned)(t0 + lane);
                pe_sh[off] = av;                              // own copy
                st_cluster_f32(pe_peer + 4 * off, av);        // peer copy
            }
        }
    }
    cluster_sync();                           // C1: both partial-e arrays everywhere

    // ---- phase 4: sum partials, mask, softmax + new_pos (warp 0, redundant) ----
    if (wid == 0) {
        float e0 = (lane < wl)      ? pe_sh[lane]      + pe_sh[TPAD + lane]      : -3.4e38f;
        float e1 = (lane + 32 < wl) ? pe_sh[lane + 32] + pe_sh[TPAD + lane + 32] : -3.4e38f;
        float e2 = (lane + 64 < wl) ? pe_sh[lane + 64] + pe_sh[TPAD + lane + 64] : -3.4e38f;
        if (lane < wl      && mk_sh[lane]      != 0.f) e0 = -1e9f;
        if (lane + 32 < wl && mk_sh[lane + 32] != 0.f) e1 = -1e9f;
        if (lane + 64 < wl && mk_sh[lane + 64] != 0.f) e2 = -1e9f;
        float m = fmaxf(e0, fmaxf(e1, e2));
        #pragma unroll
        for (int o = 16; o; o >>= 1) m = fmaxf(m, __shfl_xor_sync(0xffffffffu, m, o));
        if (m <= -1e9f) {
            if (lane == 0) s_fb = 1;
        } else {
            if (lane == 0) s_fb = 0;
            float x0 = (lane < wl)      ? __expf(e0 - m) : 0.f;
            float x1 = (lane + 32 < wl) ? __expf(e1 - m) : 0.f;
            float x2 = (lane + 64 < wl) ? __expf(e2 - m) : 0.f;
            float ssum = x0 + x1 + x2;
            float np = x0 * (float)(start + lane)
                     + x1 * (float)(start + lane + 32)
                     + x2 * (float)(start + lane + 64);
            #pragma unroll
            for (int o = 16; o; o >>= 1) {
                ssum += __shfl_xor_sync(0xffffffffu, ssum, o);
                np   += __shfl_xor_sync(0xffffffffu, np, o);
            }
            float inv = __fdividef(1.0f, ssum);
            if (lane < wl)      w_sh[lane]      = x0 * inv;
            if (lane + 32 < wl) w_sh[lane + 32] = x1 * inv;
            if (lane + 64 < wl) w_sh[lane + 64] = x2 * inv;
            if (lane == 0 && rank == 0)
                out[(size_t)BB * ENC_DIM + (size_t)BB * TT + b] = np * inv;
        }
    }
    asm volatile("cp.async.wait_group 0;");   // mem slice complete
    __syncthreads();                          // S2: w_sh + s_fb ready

    float* out_ctx = out + (size_t)b * ENC_DIM;
    float* out_w   = out + (size_t)BB * ENC_DIM + (size_t)b * TT;
    const int fb = s_fb;

    // ---- phase 5: out_w select-pass (own 1024-t half) ----
    {
        const float u = 1.0f / (float)TT;
        const int tbase = (int)rank * 1024 + tid * 4;
        float vals[4];
        #pragma unroll
        for (int j = 0; j < 4; j++) {
            const int tl = tbase + j - start;
            vals[j] = fb ? u : ((tl >= 0 && tl < wl) ? w_sh[tl] : 0.0f);
        }
        ((float4*)out_w)[rank * 256 + tid] = make_float4(vals[0], vals[1], vals[2], vals[3]);
        if (fb && rank == 0 && tid == 0)
            out[(size_t)BB * ENC_DIM + (size_t)BB * TT + b] = (float)(TT - 1) * 0.5f;
    }

    // ---- phase 6: context partial over own timestep half, DSMEM combine ----
    float4 acc = make_float4(0.f, 0.f, 0.f, 0.f);
    if (tid < 128) {
        if (!fb) {
            const float4* m4 = (const float4*)mem_sh;
            #pragma unroll 4
            for (int i = 0; i < ntl; i++) {
                const float wv = w_sh[TL0 + i];
                const float4 v = m4[i * (ENC_DIM / 4) + tid];
                acc.x += wv * v.x; acc.y += wv * v.y;
                acc.z += wv * v.z; acc.w += wv * v.w;
            }
        } else {
            const float u = 1.0f / (float)TT;
            const float4* mg = (const float4*)(memory
                + ((size_t)b * TT + (size_t)rank * 1024) * ENC_DIM);
            for (int t = 0; t < 1024; t++) {
                const float4 v = mg[(size_t)t * (ENC_DIM / 4) + tid];
                acc.x += v.x; acc.y += v.y; acc.z += v.z; acc.w += v.w;
            }
            acc.x *= u; acc.y *= u; acc.z *= u; acc.w *= u;
        }
    }
    if (rank == 1 && tid < 128) {
        const unsigned cb = mapa_peer(smem_u32(ctxbuf), peer) + tid * 16;
        st_cluster_f32(cb,      acc.x);
        st_cluster_f32(cb + 4,  acc.y);
        st_cluster_f32(cb + 8,  acc.z);
        st_cluster_f32(cb + 12, acc.w);
    }
    cluster_sync();                           // C2: rank1 partial visible
    if (rank == 0 && tid < 128) {
        const float4 p = ((const float4*)ctxbuf)[tid];
        acc.x += p.x; acc.y += p.y; acc.z += p.z; acc.w += p.w;
        ((float4*)out_ctx)[tid] = acc;
    }
}

extern "C" void kernel_launch(void* const* d_in, const int* in_sizes, int n_in,
                              void* d_out, int out_size) {
    const float*         h      = (const float*)d_in[0];
    const float*         memory = (const float*)d_in[1];
    const float*         pm     = (const float*)d_in[2];
    const float*         awcat  = (const float*)d_in[3];
    const unsigned char* maskp  = (const unsigned char*)d_in[4];
    const int*           mlen   = (const int*)d_in[5];
    const float*         cpos   = (const float*)d_in[6];
    const float*         convw  = (const float*)d_in[7];
    const float*         densew = (const float*)d_in[8];
    const float*         queryw = (const float*)d_in[9];
    const float*         vw     = (const float*)d_in[10];
    const float*         posoff = (const float*)d_in[11];
    float* out = (float*)d_out;

    cudaFuncSetAttribute(attn_fused_kernel,
                         cudaFuncAttributeMaxDynamicSharedMemorySize, SMEM_BYTES);
    attn_fused_kernel<<<2 * BB, 256, SMEM_BYTES>>>(h, memory, pm, awcat, maskp,
                                                   mlen, cpos, convw, densew,
                                                   queryw, vw, posoff, out);
}

// round 13
// speedup vs baseline: 1.3636x; 1.2386x over previous
#include <cuda_runtime.h>
#include <math.h>

#define BB 64
#define TT 2048
#define ENC_DIM 512
#define ATT_DIM 128
#define RNN_DIM 1024
#define N_FILT 32
#define KSIZE 31
#define PADC 15
#define WIN 32
#define WLMAX 65
#define TPAD 68             // padded timestep rows (mult of 4)
#define HDIM 64             // dims per rank
#define DTP 68              // dense_t row stride
#define AWLEN 98            // staged aw length per channel
#define NTHR 512

// ---- dynamic smem layout (floats), per CTA ----
#define F_MEM  0                                   // 33*512 = 16896
#define F_PM   (F_MEM + 33 * ENC_DIM)              // 68*64  = 4352
#define F_DT   (F_PM + TPAD * HDIM)                // 32*68  = 2176
#define F_CWT  (F_DT + N_FILT * DTP)               // 62*32  = 1984
#define F_H    (F_CWT + KSIZE * 2 * N_FILT)        // 1024
#define F_CONV (F_H + RNN_DIM)                     // 32*68  = 2176
#define F_AW   (F_CONV + N_FILT * TPAD)            // 2*100
#define F_Q    (F_AW + 2 * 100)                    // 64
#define F_V    (F_Q + HDIM)                        // 64
#define F_PE   (F_V + HDIM)                        // 2*68 partial e
#define F_MK   (F_PE + 2 * TPAD)                   // 68
#define F_W    (F_MK + TPAD)                       // 68
#define F_CTX4 (F_W + TPAD)                        // 4 groups * 512 = 2048
#define F_CTXP (F_CTX4 + 4 * ENC_DIM)              // 512 peer buffer
#define F_END  (F_CTXP + ENC_DIM)
#define SMEM_BYTES (F_END * 4)                     // ~128 KB

__device__ __forceinline__ float ftanh(float x) {
    float a = fabsf(x);
    float t = __expf(-2.0f * a);
    float r = __fdividef(1.0f - t, 1.0f + t);
    return copysignf(r, x);
}

__device__ __forceinline__ void cp16(unsigned dst, const void* src) {
    asm volatile("cp.async.cg.shared.global [%0], [%1], 16;" :: "r"(dst), "l"(src));
}
__device__ __forceinline__ unsigned smem_u32(const void* p) {
    return (unsigned)__cvta_generic_to_shared(p);
}
__device__ __forceinline__ unsigned mapa_peer(unsigned addr, unsigned peer) {
    unsigned r;
    asm("mapa.shared::cluster.u32 %0, %1, %2;" : "=r"(r) : "r"(addr), "r"(peer));
    return r;
}
__device__ __forceinline__ void st_cluster_f32(unsigned addr, float v) {
    asm volatile("st.shared::cluster.f32 [%0], %1;" :: "r"(addr), "f"(v));
}
__device__ __forceinline__ void cluster_sync() {
    asm volatile("barrier.cluster.arrive.aligned;" ::: "memory");
    asm volatile("barrier.cluster.wait.aligned;" ::: "memory");
}

__global__ __launch_bounds__(NTHR, 1) __cluster_dims__(2, 1, 1)
void attn_fused_kernel(
    const float* __restrict__ h,
    const float* __restrict__ memory,
    const float* __restrict__ pm,
    const float* __restrict__ awcat,
    const unsigned char* __restrict__ maskp,
    const int* __restrict__ mlen,
    const float* __restrict__ cpos,
    const float* __restrict__ convw,
    const float* __restrict__ densew,
    const float* __restrict__ queryw,
    const float* __restrict__ vw,
    const float* __restrict__ posoff,
    float* __restrict__ out)
{
    extern __shared__ float sm[];
    __shared__ int s_fb;

    const int b    = blockIdx.x >> 1;
    const unsigned rank = blockIdx.x & 1;
    const unsigned peer = rank ^ 1;
    const int tid  = threadIdx.x;
    const int lane = tid & 31;
    const int wid  = tid >> 5;          // 0..15

    float* mem_sh  = sm + F_MEM;
    float* pm_sh   = sm + F_PM;
    float* dense_t = sm + F_DT;
    float* cwt_sh  = sm + F_CWT;
    float* h_sh    = sm + F_H;
    float* conv_sh = sm + F_CONV;
    float* aw0_sh  = sm + F_AW;
    float* aw1_sh  = sm + F_AW + 100;
    float* q_sh    = sm + F_Q;
    float* v_sh    = sm + F_V;
    float* pe_sh   = sm + F_PE;
    float* mk_sh   = sm + F_MK;
    float* w_sh    = sm + F_W;
    float* ctx4    = sm + F_CTX4;       // [4][ENC_DIM] row-group partials
    float* ctxp    = sm + F_CTXP;       // peer combine buffer

    // ---- phase 0a: every thread computes the window (broadcast LDGs) ----
    int start, wl;
    {
        float cp      = cpos[b] + posoff[0];
        float max_end = (float)(mlen[b] - 1 - WIN);
        cp = fminf(fmaxf(cp, (float)WIN), max_end);
        float ms = rintf(fmaxf(cp - (float)WIN, 0.0f));
        start = (int)ms;
        if (start < 0) start = 0;
        if (start > TT - 1) start = TT - 1;
        int end = start + 2 * WIN;
        if (end > TT - 1) end = TT - 1;
        wl = end - start + 1;           // == 65 for this shape
    }
    const int TL0 = rank ? 33 : 0;
    int ntl = rank ? (wl - 33) : (wl < 33 ? wl : 33);
    if (ntl < 0) ntl = 0;

    // ---- phase 0b: prefetch immediately (no preceding barrier) ----
    {
        const unsigned pm_base  = smem_u32(pm_sh);
        const unsigned mem_base = smem_u32(mem_sh);
        const float* pmsrc = pm + ((size_t)b * TT + start) * ATT_DIM + rank * HDIM;
        const int n_pmc = wl * (HDIM / 4);
        for (int i = tid; i < n_pmc; i += NTHR) {
            const int row = i >> 4, col = i & 15;
            cp16(pm_base + (unsigned)(row * (HDIM * 4) + col * 16),
                 pmsrc + (size_t)row * ATT_DIM + col * 4);
        }
        asm volatile("cp.async.commit_group;");
        const float4* memsrc = (const float4*)(memory + ((size_t)b * TT + start + TL0) * ENC_DIM);
        const int n_m4 = ntl * (ENC_DIM / 4);
        for (int i = tid; i < n_m4; i += NTHR) cp16(mem_base + i * 16, memsrc + i);
        asm volatile("cp.async.commit_group;");

        for (int j = tid; j < 2 * AWLEN; j += NTHR) {
            int c = (j >= AWLEN), jj = c ? j - AWLEN : j;
            int g = start - PADC + jj;
            float v = (g >= 0 && g < TT) ? awcat[((size_t)b * 2 + c) * TT + g] : 0.f;
            (c ? aw1_sh : aw0_sh)[jj] = v;
        }
        if (tid < wl) mk_sh[tid] = maskp[(size_t)b * TT + start + tid] ? 1.f : 0.f;
    }

    // ---- phase 0c: stage static weights (own-dim slices) ----
    {
        if (tid < 256) {
            const float4* hg = (const float4*)(h + (size_t)b * RNN_DIM);
            ((float4*)h_sh)[tid] = hg[tid];
        }
        for (int i = tid; i < N_FILT * 2 * KSIZE; i += NTHR) {
            int f = i / (2 * KSIZE), rr = i % (2 * KSIZE);
            int c = rr / KSIZE, k = rr % KSIZE;
            cwt_sh[(k * 2 + c) * N_FILT + f] = convw[i];
        }
        for (int i = tid; i < HDIM * N_FILT; i += NTHR) {
            int al = i >> 5, f = i & 31;
            dense_t[f * DTP + al] = densew[((size_t)rank * HDIM + al) * N_FILT + f];
        }
        if (tid < HDIM) v_sh[tid] = vw[rank * HDIM + tid];
    }
    __syncthreads();                    // S0

    // ---- phase 1: query GEMV — own 64 rows, 4 per warp, 4-row ILP ----
    {
        const float4* h4 = (const float4*)h_sh;
        const int al0 = wid * 4;                         // local q index
        const int a0  = rank * HDIM + al0;               // global row
        const float4* r0 = (const float4*)(queryw + (size_t)a0 * RNN_DIM);
        const float4* r1 = (const float4*)(queryw + (size_t)(a0 + 1) * RNN_DIM);
        const float4* r2 = (const float4*)(queryw + (size_t)(a0 + 2) * RNN_DIM);
        const float4* r3 = (const float4*)(queryw + (size_t)(a0 + 3) * RNN_DIM);
        float acc0 = 0.f, acc1 = 0.f, acc2 = 0.f, acc3 = 0.f;
        #pragma unroll
        for (int k = 0; k < 8; k++) {
            const int idx = lane + k * 32;
            float4 hv = h4[idx];
            float4 w0 = r0[idx], w1 = r1[idx], w2 = r2[idx], w3 = r3[idx];
            acc0 += hv.x * w0.x + hv.y * w0.y + hv.z * w0.z + hv.w * w0.w;
            acc1 += hv.x * w1.x + hv.y * w1.y + hv.z * w1.z + hv.w * w1.w;
            acc2 += hv.x * w2.x + hv.y * w2.y + hv.z * w2.z + hv.w * w2.w;
            acc3 += hv.x * w3.x + hv.y * w3.y + hv.z * w3.z + hv.w * w3.w;
        }
        #pragma unroll
        for (int o = 16; o; o >>= 1) {
            acc0 += __shfl_down_sync(0xffffffffu, acc0, o);
            acc1 += __shfl_down_sync(0xffffffffu, acc1, o);
            acc2 += __shfl_down_sync(0xffffffffu, acc2, o);
            acc3 += __shfl_down_sync(0xffffffffu, acc3, o);
        }
        if (lane == 0) {
            q_sh[al0] = acc0; q_sh[al0 + 1] = acc1;
            q_sh[al0 + 2] = acc2; q_sh[al0 + 3] = acc3;
        }
    }

    // ---- phase 2: conv — all timesteps, 2 filters/warp, tl padded 0..67 ----
    {
        const int f0 = wid * 2;
        for (int tl = lane; tl < TPAD; tl += 32) {
            float a0c = 0.f, a1c = 0.f;
            #pragma unroll
            for (int k = 0; k < KSIZE; k++) {
                const float x0 = aw0_sh[tl + k];
                const float x1 = aw1_sh[tl + k];
                const float2 w0 = *(const float2*)(cwt_sh + (k * 2 + 0) * N_FILT + f0);
                const float2 w1 = *(const float2*)(cwt_sh + (k * 2 + 1) * N_FILT + f0);
                a0c += x0 * w0.x + x1 * w1.x;
                a1c += x0 * w0.y + x1 * w1.y;
            }
            conv_sh[f0 * TPAD + tl]       = a0c;
            conv_sh[(f0 + 1) * TPAD + tl] = a1c;
        }
    }
    asm volatile("cp.async.wait_group 1;");   // pm slice (this thread)
    __syncthreads();                          // S1: q + conv + pm ready

    // ---- phase 3: partial energies over own 64 dims, all timesteps ----
    {
        const unsigned pe_peer = mapa_peer(smem_u32(pe_sh), peer);
        const float qv0 = q_sh[lane], qv1 = q_sh[lane + 32];
        const float vv0 = v_sh[lane], vv1 = v_sh[lane + 32];
        for (int t0 = wid * 4; t0 < wl; t0 += 64) {
            float s[4][2];
            #pragma unroll
            for (int i = 0; i < 4; i++) {
                const float* p = pm_sh + (t0 + i) * HDIM;   // padded rows safe
                s[i][0] = qv0 + p[lane];
                s[i][1] = qv1 + p[lane + 32];
            }
            #pragma unroll 8
            for (int f = 0; f < N_FILT; f++) {
                const float4 c4 = *(const float4*)(conv_sh + f * TPAD + t0);
                const float* dt = dense_t + f * DTP;
                const float d0 = dt[lane], d1 = dt[lane + 32];
                s[0][0] += d0 * c4.x; s[0][1] += d1 * c4.x;
                s[1][0] += d0 * c4.y; s[1][1] += d1 * c4.y;
                s[2][0] += d0 * c4.z; s[2][1] += d1 * c4.z;
                s[3][0] += d0 * c4.w; s[3][1] += d1 * c4.w;
            }
            float a[4];
            #pragma unroll
            for (int i = 0; i < 4; i++)
                a[i] = vv0 * ftanh(s[i][0]) + vv1 * ftanh(s[i][1]);
            #pragma unroll
            for (int o = 16; o; o >>= 1) {
                a[0] += __shfl_xor_sync(0xffffffffu, a[0], o);
                a[1] += __shfl_xor_sync(0xffffffffu, a[1], o);
                a[2] += __shfl_xor_sync(0xffffffffu, a[2], o);
                a[3] += __shfl_xor_sync(0xffffffffu, a[3], o);
            }
            if (lane < 4 && t0 + lane < wl) {
                const float av = (lane == 0) ? a[0] : (lane == 1) ? a[1]
                               : (lane == 2) ? a[2] : a[3];
                const unsigned off = rank * TPAD + (unsigned)(t0 + lane);
                pe_sh[off] = av;
                st_cluster_f32(pe_peer + 4 * off, av);
            }
        }
    }
    cluster_sync();                           // C1: both partial-e arrays everywhere

    // ---- phase 4: sum partials, mask, softmax + new_pos (warp 0) ----
    if (wid == 0) {
        float e0 = (lane < wl)      ? pe_sh[lane]      + pe_sh[TPAD + lane]      : -3.4e38f;
        float e1 = (lane + 32 < wl) ? pe_sh[lane + 32] + pe_sh[TPAD + lane + 32] : -3.4e38f;
        float e2 = (lane + 64 < wl) ? pe_sh[lane + 64] + pe_sh[TPAD + lane + 64] : -3.4e38f;
        if (lane < wl      && mk_sh[lane]      != 0.f) e0 = -1e9f;
        if (lane + 32 < wl && mk_sh[lane + 32] != 0.f) e1 = -1e9f;
        if (lane + 64 < wl && mk_sh[lane + 64] != 0.f) e2 = -1e9f;
        float m = fmaxf(e0, fmaxf(e1, e2));
        #pragma unroll
        for (int o = 16; o; o >>= 1) m = fmaxf(m, __shfl_xor_sync(0xffffffffu, m, o));
        if (m <= -1e9f) {
            if (lane == 0) s_fb = 1;
        } else {
            if (lane == 0) s_fb = 0;
            float x0 = (lane < wl)      ? __expf(e0 - m) : 0.f;
            float x1 = (lane + 32 < wl) ? __expf(e1 - m) : 0.f;
            float x2 = (lane + 64 < wl) ? __expf(e2 - m) : 0.f;
            float ssum = x0 + x1 + x2;
            float np = x0 * (float)(start + lane)
                     + x1 * (float)(start + lane + 32)
                     + x2 * (float)(start + lane + 64);
            #pragma unroll
            for (int o = 16; o; o >>= 1) {
                ssum += __shfl_xor_sync(0xffffffffu, ssum, o);
                np   += __shfl_xor_sync(0xffffffffu, np, o);
            }
            float inv = __fdividef(1.0f, ssum);
            if (lane < wl)      w_sh[lane]      = x0 * inv;
            if (lane + 32 < wl) w_sh[lane + 32] = x1 * inv;
            if (lane + 64 < wl) w_sh[lane + 64] = x2 * inv;
            if (lane == 0 && rank == 0)
                out[(size_t)BB * ENC_DIM + (size_t)BB * TT + b] = np * inv;
        }
    }
    asm volatile("cp.async.wait_group 0;");   // mem slice complete
    __syncthreads();                          // S2: w_sh + s_fb ready

    float* out_ctx = out + (size_t)b * ENC_DIM;
    float* out_w   = out + (size_t)BB * ENC_DIM + (size_t)b * TT;
    const int fb = s_fb;

    // ---- phase 5: out_w select-pass (own half, tid<256 x float4) ----
    if (tid < 256) {
        const float u = 1.0f / (float)TT;
        const int tbase = (int)rank * 1024 + tid * 4;
        float vals[4];
        #pragma unroll
        for (int j = 0; j < 4; j++) {
            const int tl = tbase + j - start;
            vals[j] = fb ? u : ((tl >= 0 && tl < wl) ? w_sh[tl] : 0.0f);
        }
        ((float4*)out_w)[rank * 256 + tid] = make_float4(vals[0], vals[1], vals[2], vals[3]);
        if (fb && rank == 0 && tid == 0)
            out[(size_t)BB * ENC_DIM + (size_t)BB * TT + b] = (float)(TT - 1) * 0.5f;
    }

    // ---- phase 6: context — 4 row-groups x 128 cols, tree combine ----
    {
        const int c   = tid & 127;
        const int grp = tid >> 7;             // 0..3
        float4 acc = make_float4(0.f, 0.f, 0.f, 0.f);
        if (!fb) {
            const int i0 = (ntl * grp) >> 2;
            const int i1 = (ntl * (grp + 1)) >> 2;
            const float4* m4 = (const float4*)mem_sh;
            for (int i = i0; i < i1; i++) {
                const float wv = w_sh[TL0 + i];
                const float4 v = m4[i * (ENC_DIM / 4) + c];
                acc.x += wv * v.x; acc.y += wv * v.y;
                acc.z += wv * v.z; acc.w += wv * v.w;
            }
        } else {
            const float u = 1.0f / (float)TT;
            const int r0 = (int)rank * 1024 + grp * 256;
            const float4* mg = (const float4*)(memory + ((size_t)b * TT + r0) * ENC_DIM);
            for (int t = 0; t < 256; t++) {
                const float4 v = mg[(size_t)t * (ENC_DIM / 4) + c];
                acc.x += v.x; acc.y += v.y; acc.z += v.z; acc.w += v.w;
            }
            acc.x *= u; acc.y *= u; acc.z *= u; acc.w *= u;
        }
        ((float4*)ctx4)[grp * 128 + c] = acc;
    }
    __syncthreads();                          // S3: group partials in ctx4

    if (tid < 128) {
        const float4 p0 = ((const float4*)ctx4)[tid];
        const float4 p1 = ((const float4*)ctx4)[128 + tid];
        const float4 p2 = ((const float4*)ctx4)[256 + tid];
        const float4 p3 = ((const float4*)ctx4)[384 + tid];
        float4 acc = make_float4(p0.x + p1.x + p2.x + p3.x,
                                 p0.y + p1.y + p2.y + p3.y,
                                 p0.z + p1.z + p2.z + p3.z,
                                 p0.w + p1.w + p2.w + p3.w);
        if (rank == 1) {
            const unsigned cb = mapa_peer(smem_u32(ctxp), peer) + tid * 16;
            st_cluster_f32(cb,      acc.x);
            st_cluster_f32(cb + 4,  acc.y);
            st_cluster_f32(cb + 8,  acc.z);
            st_cluster_f32(cb + 12, acc.w);
        } else {
            ((float4*)ctx4)[tid] = acc;       // stash own partial
        }
    }
    cluster_sync();                           // C2: rank1 partial visible
    if (rank == 0 && tid < 128) {
        const float4 a0 = ((const float4*)ctx4)[tid];
        const float4 p  = ((const float4*)ctxp)[tid];
        ((float4*)out_ctx)[tid] = make_float4(a0.x + p.x, a0.y + p.y,
                                              a0.z + p.z, a0.w + p.w);
    }
}

extern "C" void kernel_launch(void* const* d_in, const int* in_sizes, int n_in,
                              void* d_out, int out_size) {
    const float*         h      = (const float*)d_in[0];
    const float*         memory = (const float*)d_in[1];
    const float*         pm     = (const float*)d_in[2];
    const float*         awcat  = (const float*)d_in[3];
    const unsigned char* maskp  = (const unsigned char*)d_in[4];
    const int*           mlen   = (const int*)d_in[5];
    const float*         cpos   = (const float*)d_in[6];
    const float*         convw  = (const float*)d_in[7];
    const float*         densew = (const float*)d_in[8];
    const float*         queryw = (const float*)d_in[9];
    const float*         vw     = (const float*)d_in[10];
    const float*         posoff = (const float*)d_in[11];
    float* out = (float*)d_out;

    cudaFuncSetAttribute(attn_fused_kernel,
                         cudaFuncAttributeMaxDynamicSharedMemorySize, SMEM_BYTES);
    attn_fused_kernel<<<2 * BB, NTHR, SMEM_BYTES>>>(h, memory, pm, awcat, maskp,
                                                    mlen, cpos, convw, densew,
                                                    queryw, vw, posoff, out);
}